// round 1
// baseline (speedup 1.0000x reference)
#include <cuda_runtime.h>
#include <math.h>

#define BB 4
#define SS 4096
#define DD 256
#define HH 400
#define BSROWS (BB*SS)

// ---- scratch (static device arrays; no allocation allowed) ----
__device__ float g_Q[BSROWS*DD];
__device__ float g_K[BSROWS*DD];
__device__ float g_V[BSROWS*DD];
__device__ float g_T[BSROWS*DD];   // attn out / ff out
__device__ float g_X[BSROWS*DD];
__device__ float g_Y[BSROWS*DD];
__device__ float g_H[BSROWS*HH];

// ============================================================
// Tiled fp32 GEMM: C[M,N] = A[M,K] * W[K,N] (+bias, +leaky)
// BM=64, BN=64, BK=16, 256 threads, 4x4 microtile per thread.
// Requires M%64==0 and K%16==0 (true for all our calls); N guarded.
// ============================================================
template<int BIAS, int LEAKY>
__global__ void gemm_kernel(const float* __restrict__ A, const float* __restrict__ W,
                            const float* __restrict__ bias, float* __restrict__ C,
                            int M, int N, int K) {
    __shared__ float As[16][64];
    __shared__ float Bs[16][64];
    int tid = threadIdx.x;
    int tx = tid & 15, ty = tid >> 4;
    int rowBase = blockIdx.y * 64;
    int colBase = blockIdx.x * 64;

    float acc[4][4] = {};
    for (int k0 = 0; k0 < K; k0 += 16) {
        #pragma unroll
        for (int p = 0; p < 4; p++) {
            int idx = tid + p * 256;
            int m = idx >> 4, kk = idx & 15;
            As[kk][m] = A[(rowBase + m) * K + k0 + kk];
        }
        #pragma unroll
        for (int p = 0; p < 4; p++) {
            int idx = tid + p * 256;
            int kk = idx >> 6, c = idx & 63;
            int col = colBase + c;
            Bs[kk][c] = (col < N) ? W[(k0 + kk) * N + col] : 0.0f;
        }
        __syncthreads();
        #pragma unroll
        for (int kk = 0; kk < 16; kk++) {
            float a[4], b[4];
            #pragma unroll
            for (int i = 0; i < 4; i++) a[i] = As[kk][ty * 4 + i];
            #pragma unroll
            for (int j = 0; j < 4; j++) b[j] = Bs[kk][tx * 4 + j];
            #pragma unroll
            for (int i = 0; i < 4; i++)
                #pragma unroll
                for (int j = 0; j < 4; j++)
                    acc[i][j] = fmaf(a[i], b[j], acc[i][j]);
        }
        __syncthreads();
    }
    #pragma unroll
    for (int i = 0; i < 4; i++) {
        int row = rowBase + ty * 4 + i;
        #pragma unroll
        for (int j = 0; j < 4; j++) {
            int col = colBase + tx * 4 + j;
            if (col < N) {
                float v = acc[i][j];
                if (BIAS) v += bias[col];
                if (LEAKY) v = (v > 0.0f) ? v : 0.2f * v;
                C[row * N + col] = v;
            }
        }
    }
}

// ============================================================
// Flash attention, fp32, online softmax.
// Block = 256 threads handles BQ=64 queries; streams K/V in BK=32 chunks.
// SMEM rows padded to 260 floats (65 float4) for bank-conflict relief.
// O accumulator lives in registers: 4 threads per row, 16 float4 each,
// interleaved by float4 (thread s owns chunks 4i+s) so V reads are
// conflict-free broadcasts.
// ============================================================
#define BQ 64
#define BK 32
#define LDR 65   // float4 stride per smem row (=260 floats)

__global__ void flash_kernel(const float* __restrict__ Qg, const float* __restrict__ Kg,
                             const float* __restrict__ Vg, float* __restrict__ Og,
                             int causal) {
    extern __shared__ float sm[];
    float* Qs = sm;                       // 64*260
    float* Ks = Qs + BQ * 260;            // 32*260
    float* Vs = Ks + BK * 260;            // 32*260
    float* Ssm = Vs + BK * 260;           // 64*33
    float* m_s = Ssm + 64 * 33;
    float* l_s = m_s + 64;
    float* a_s = l_s + 64;

    int tid = threadIdx.x;
    int b = blockIdx.y;
    int q0 = blockIdx.x * BQ;

    const float4* Q4 = (const float4*)(Qg + (size_t)b * SS * DD) + (size_t)q0 * (DD / 4);
    const float4* K4 = (const float4*)(Kg + (size_t)b * SS * DD);
    const float4* V4 = (const float4*)(Vg + (size_t)b * SS * DD);
    float4* Qs4 = (float4*)Qs;
    float4* Ks4 = (float4*)Ks;
    float4* Vs4 = (float4*)Vs;

    // load Q tile (64 x 256 floats = 4096 float4)
    #pragma unroll
    for (int p = 0; p < 16; p++) {
        int idx = tid + p * 256;
        int r = idx >> 6, d4 = idx & 63;
        Qs4[r * LDR + d4] = Q4[r * 64 + d4];
    }
    if (tid < BQ) { m_s[tid] = -INFINITY; l_s[tid] = 0.0f; }

    int tx = tid & 15, ty = tid >> 4;     // score phase: rows ty*4+i, cols tx+16j
    int r_pv = tid >> 2, s_pv = tid & 3;  // PV phase: 4 threads per row

    float4 o[16];
    #pragma unroll
    for (int i = 0; i < 16; i++) o[i] = make_float4(0.f, 0.f, 0.f, 0.f);

    const float scale = 1.0f / 64.0f;     // 1/sqrt(4096)
    int kend = causal ? (q0 + BQ) : SS;

    for (int k0 = 0; k0 < kend; k0 += BK) {
        __syncthreads();  // protects Ks/Vs reuse + initial Q/m/l init
        // load K,V chunk (32 x 256 floats = 2048 float4 each)
        #pragma unroll
        for (int p = 0; p < 8; p++) {
            int idx = tid + p * 256;
            int r = idx >> 6, d4 = idx & 63;
            Ks4[r * LDR + d4] = K4[(k0 + r) * 64 + d4];
            Vs4[r * LDR + d4] = V4[(k0 + r) * 64 + d4];
        }
        __syncthreads();

        // scores: S[64][32] = Q . K^T
        float acc[4][2] = {};
        #pragma unroll 4
        for (int d4 = 0; d4 < 64; d4++) {
            float4 qa[4], kb[2];
            #pragma unroll
            for (int i = 0; i < 4; i++) qa[i] = Qs4[(ty * 4 + i) * LDR + d4];
            #pragma unroll
            for (int j = 0; j < 2; j++) kb[j] = Ks4[(tx + 16 * j) * LDR + d4];
            #pragma unroll
            for (int i = 0; i < 4; i++)
                #pragma unroll
                for (int j = 0; j < 2; j++) {
                    acc[i][j] = fmaf(qa[i].x, kb[j].x, acc[i][j]);
                    acc[i][j] = fmaf(qa[i].y, kb[j].y, acc[i][j]);
                    acc[i][j] = fmaf(qa[i].z, kb[j].z, acc[i][j]);
                    acc[i][j] = fmaf(qa[i].w, kb[j].w, acc[i][j]);
                }
        }
        #pragma unroll
        for (int i = 0; i < 4; i++) {
            int r = ty * 4 + i;
            #pragma unroll
            for (int j = 0; j < 2; j++) {
                int c = tx + 16 * j;
                float v = acc[i][j] * scale;
                if (causal && (k0 + c > q0 + r)) v = -1e30f;
                Ssm[r * 33 + c] = v;
            }
        }
        __syncthreads();

        // online softmax per row
        if (tid < BQ) {
            int r = tid;
            float cmax = -1e30f;
            #pragma unroll
            for (int c = 0; c < BK; c++) cmax = fmaxf(cmax, Ssm[r * 33 + c]);
            float mold = m_s[r];
            float mnew = fmaxf(mold, cmax);
            float alpha = __expf(mold - mnew);
            float sum = 0.0f;
            #pragma unroll
            for (int c = 0; c < BK; c++) {
                float p = __expf(Ssm[r * 33 + c] - mnew);
                Ssm[r * 33 + c] = p;
                sum += p;
            }
            l_s[r] = l_s[r] * alpha + sum;
            m_s[r] = mnew;
            a_s[r] = alpha;
        }
        __syncthreads();

        // O = O*alpha + P . V
        float alpha = a_s[r_pv];
        #pragma unroll
        for (int i = 0; i < 16; i++) {
            o[i].x *= alpha; o[i].y *= alpha; o[i].z *= alpha; o[i].w *= alpha;
        }
        #pragma unroll 4
        for (int c = 0; c < BK; c++) {
            float p = Ssm[r_pv * 33 + c];
            #pragma unroll
            for (int i = 0; i < 16; i++) {
                float4 v = Vs4[c * LDR + 4 * i + s_pv];
                o[i].x = fmaf(p, v.x, o[i].x);
                o[i].y = fmaf(p, v.y, o[i].y);
                o[i].z = fmaf(p, v.z, o[i].z);
                o[i].w = fmaf(p, v.w, o[i].w);
            }
        }
    }
    __syncthreads();

    float inv = 1.0f / l_s[r_pv];
    float4* O4 = (float4*)(Og + (size_t)b * SS * DD) + (size_t)(q0 + r_pv) * (DD / 4);
    #pragma unroll
    for (int i = 0; i < 16; i++) {
        float4 v = o[i];
        v.x *= inv; v.y *= inv; v.z *= inv; v.w *= inv;
        O4[4 * i + s_pv] = v;
    }
}

// ============================================================
// out = LayerNorm(a + b) with gamma/beta, eps = 1e-3
// one block (256 threads) per row of 256 elems
// ============================================================
__global__ void add_ln_kernel(const float* __restrict__ a, const float* __restrict__ bvec,
                              const float* __restrict__ gamma, const float* __restrict__ beta,
                              float* __restrict__ out) {
    int row = blockIdx.x;
    int d = threadIdx.x;
    float v = a[row * DD + d] + bvec[row * DD + d];

    __shared__ float red[8];
    float sum = v;
    #pragma unroll
    for (int off = 16; off > 0; off >>= 1) sum += __shfl_xor_sync(0xffffffff, sum, off);
    if ((d & 31) == 0) red[d >> 5] = sum;
    __syncthreads();
    float tot = 0.0f;
    #pragma unroll
    for (int i = 0; i < 8; i++) tot += red[i];
    float mu = tot * (1.0f / DD);

    float dv = v - mu;
    float sq = dv * dv;
    #pragma unroll
    for (int off = 16; off > 0; off >>= 1) sq += __shfl_xor_sync(0xffffffff, sq, off);
    __syncthreads();
    if ((d & 31) == 0) red[d >> 5] = sq;
    __syncthreads();
    float var = 0.0f;
    #pragma unroll
    for (int i = 0; i < 8; i++) var += red[i];
    var *= (1.0f / DD);

    out[row * DD + d] = dv * rsqrtf(var + 1e-3f) * gamma[d] + beta[d];
}

// ============================================================
extern "C" void kernel_launch(void* const* d_in, const int* in_sizes, int n_in,
                              void* d_out, int out_size) {
    const float* inputs = (const float*)d_in[0];
    const float* ctx    = (const float*)d_in[1];
    const float* sa_Wk  = (const float*)d_in[2];
    const float* sa_Wv  = (const float*)d_in[3];
    const float* sa_Wq  = (const float*)d_in[4];
    const float* ca_Wk  = (const float*)d_in[5];
    const float* ca_Wv  = (const float*)d_in[6];
    const float* ca_Wq  = (const float*)d_in[7];
    const float* W1     = (const float*)d_in[8];
    const float* b1     = (const float*)d_in[9];
    const float* W2     = (const float*)d_in[10];
    const float* b2     = (const float*)d_in[11];
    const float* gamma  = (const float*)d_in[12];
    const float* beta   = (const float*)d_in[13];
    float* out = (float*)d_out;

    float *Qp, *Kp, *Vp, *Tp, *Xp, *Yp, *Hp;
    cudaGetSymbolAddress((void**)&Qp, g_Q);
    cudaGetSymbolAddress((void**)&Kp, g_K);
    cudaGetSymbolAddress((void**)&Vp, g_V);
    cudaGetSymbolAddress((void**)&Tp, g_T);
    cudaGetSymbolAddress((void**)&Xp, g_X);
    cudaGetSymbolAddress((void**)&Yp, g_Y);
    cudaGetSymbolAddress((void**)&Hp, g_H);

    size_t flash_smem = (size_t)(BQ * 260 + 2 * BK * 260 + 64 * 33 + 3 * 64) * sizeof(float);
    cudaFuncSetAttribute(flash_kernel, cudaFuncAttributeMaxDynamicSharedMemorySize, (int)flash_smem);

    dim3 gD(DD / 64, BSROWS / 64);           // projections: N=256
    dim3 gH((HH + 63) / 64, BSROWS / 64);    // FFN up: N=400
    dim3 fg(SS / BQ, BB);

    // 1) self-attention (causal)
    gemm_kernel<0, 0><<<gD, 256>>>(inputs, sa_Wk, nullptr, Kp, BSROWS, DD, DD);
    gemm_kernel<0, 0><<<gD, 256>>>(inputs, sa_Wv, nullptr, Vp, BSROWS, DD, DD);
    gemm_kernel<0, 0><<<gD, 256>>>(inputs, sa_Wq, nullptr, Qp, BSROWS, DD, DD);
    flash_kernel<<<fg, 256, flash_smem>>>(Qp, Kp, Vp, Tp, 1);
    add_ln_kernel<<<BSROWS, 256>>>(Tp, inputs, gamma, beta, Xp);

    // 2) cross-attention (no mask)
    gemm_kernel<0, 0><<<gD, 256>>>(ctx, ca_Wk, nullptr, Kp, BSROWS, DD, DD);
    gemm_kernel<0, 0><<<gD, 256>>>(ctx, ca_Wv, nullptr, Vp, BSROWS, DD, DD);
    gemm_kernel<0, 0><<<gD, 256>>>(Xp, ca_Wq, nullptr, Qp, BSROWS, DD, DD);
    flash_kernel<<<fg, 256, flash_smem>>>(Qp, Kp, Vp, Tp, 0);
    add_ln_kernel<<<BSROWS, 256>>>(Tp, Xp, gamma, beta, Yp);

    // 3) FFN
    gemm_kernel<1, 1><<<gH, 256>>>(Yp, W1, b1, Hp, BSROWS, HH, DD);
    gemm_kernel<1, 0><<<gD, 256>>>(Hp, W2, b2, Tp, BSROWS, DD, HH);
    add_ln_kernel<<<BSROWS, 256>>>(Tp, Yp, gamma, beta, out);
}

// round 3
// speedup vs baseline: 6.6375x; 6.6375x over previous
#include <cuda_runtime.h>
#include <cstdint>
#include <math.h>

#define BB 4
#define SS 4096
#define DD 256
#define HH 400
#define BSROWS (BB*SS)

// ---- scratch ----
__device__ float g_Q[BSROWS*DD];
__device__ float g_K[BSROWS*DD];
__device__ float g_V[BSROWS*DD];
__device__ float g_T[BSROWS*DD];
__device__ float g_X[BSROWS*DD];
__device__ float g_Y[BSROWS*DD];
__device__ float g_H[BSROWS*HH];

// ============================================================
// helpers
// ============================================================
__device__ __forceinline__ float tf32r(float x) {
    float r; asm("cvt.rna.tf32.f32 %0, %1;" : "=f"(r) : "f"(x)); return r;
}

// m16n8k8 tf32 MMA: D += A(16x8) * B(8x8); A row-major, B "col" fragment.
__device__ __forceinline__ void mma8(float c[4], const uint32_t a[4], const uint32_t b[2]) {
    asm volatile(
        "mma.sync.aligned.m16n8k8.row.col.f32.tf32.tf32.f32 "
        "{%0,%1,%2,%3}, {%4,%5,%6,%7}, {%8,%9}, {%0,%1,%2,%3};"
        : "+f"(c[0]), "+f"(c[1]), "+f"(c[2]), "+f"(c[3])
        : "r"(a[0]), "r"(a[1]), "r"(a[2]), "r"(a[3]), "r"(b[0]), "r"(b[1]));
}

__device__ __forceinline__ uint32_t f2u(float x) { return __float_as_uint(x); }

// ============================================================
// Flash attention on HMMA tf32.
// CTA: 64 queries, 256 threads (8 warps = 4 row-groups x 2 halves).
// Streams keys in chunks of 64.
// ============================================================
#define FBQ 64
#define FBK 64
#define QSTR 260
#define KSTR 260
#define VSTR 264
#define SSTR 68
// float offsets in dynamic smem
#define OQ 0
#define OKo 16640              // 64*260
#define OV 33280               // + 64*260
#define OS 50176               // + 64*264
#define OM 54528               // + 64*68
#define OL 54592
#define OA 54656
#define FL_FLOATS 54720        // *4 = 218880 bytes

__global__ void __launch_bounds__(256, 1)
flash_mma(const float* __restrict__ Qg, const float* __restrict__ Kg,
          const float* __restrict__ Vg, float* __restrict__ Og, int causal) {
    extern __shared__ float fs[];
    int tid = threadIdx.x;
    int wid = tid >> 5, lane = tid & 31;
    int rg = wid & 3;          // row-group: rows 16*rg .. +15
    int h  = wid >> 2;         // half: cols 32h (scores) / 128h (PV)
    int lrow = lane >> 2;      // 0..7
    int lcol = lane & 3;       // 0..3
    int b = blockIdx.y, q0 = blockIdx.x * FBQ;

    // ---- stage Q (prescaled by 1/sqrt(4096)=1/64, tf32) ----
    {
        const float4* Qr = (const float4*)(Qg + ((size_t)b * SS + q0) * DD);
        #pragma unroll
        for (int p = 0; p < 16; p++) {
            int idx = tid + p * 256;
            int r = idx >> 6, c4 = idx & 63;
            float4 v = Qr[r * 64 + c4];
            v.x = tf32r(v.x * 0.015625f); v.y = tf32r(v.y * 0.015625f);
            v.z = tf32r(v.z * 0.015625f); v.w = tf32r(v.w * 0.015625f);
            *(float4*)&fs[OQ + r * QSTR + c4 * 4] = v;
        }
    }
    if (tid < FBQ) { fs[OM + tid] = -INFINITY; fs[OL + tid] = 0.0f; }

    float ofrag[16][4];
    #pragma unroll
    for (int nb = 0; nb < 16; nb++)
        #pragma unroll
        for (int j = 0; j < 4; j++) ofrag[nb][j] = 0.0f;

    int nc = causal ? (q0 / FBK + 1) : (SS / FBK);

    for (int c = 0; c < nc; c++) {
        int k0 = c * FBK;
        bool maskc = causal && (k0 == q0);

        // ---- stage K (tf32) and V (tf32) ----
        const float4* Kr = (const float4*)(Kg + ((size_t)b * SS + k0) * DD);
        const float4* Vr = (const float4*)(Vg + ((size_t)b * SS + k0) * DD);
        #pragma unroll
        for (int p = 0; p < 16; p++) {
            int idx = tid + p * 256;
            int r = idx >> 6, c4 = idx & 63;
            float4 v = Kr[r * 64 + c4];
            v.x = tf32r(v.x); v.y = tf32r(v.y); v.z = tf32r(v.z); v.w = tf32r(v.w);
            *(float4*)&fs[OKo + r * KSTR + c4 * 4] = v;
            float4 w = Vr[r * 64 + c4];
            w.x = tf32r(w.x); w.y = tf32r(w.y); w.z = tf32r(w.z); w.w = tf32r(w.w);
            *(float4*)&fs[OV + r * VSTR + c4 * 4] = w;
        }
        __syncthreads();   // (A) staging visible

        // ---- scores: warp (rg,h) computes S[16rg..+15][32h..+31] ----
        {
            float sfrag[4][4];
            #pragma unroll
            for (int nb = 0; nb < 4; nb++)
                #pragma unroll
                for (int j = 0; j < 4; j++) sfrag[nb][j] = 0.0f;

            int qrow = 16 * rg + lrow;
            #pragma unroll 4
            for (int kb = 0; kb < 32; kb++) {
                int kk = kb * 8 + lcol;
                uint32_t a[4];
                a[0] = f2u(fs[OQ + qrow * QSTR + kk]);
                a[1] = f2u(fs[OQ + (qrow + 8) * QSTR + kk]);
                a[2] = f2u(fs[OQ + qrow * QSTR + kk + 4]);
                a[3] = f2u(fs[OQ + (qrow + 8) * QSTR + kk + 4]);
                #pragma unroll
                for (int nb = 0; nb < 4; nb++) {
                    int nrow = 32 * h + nb * 8 + lrow;   // key index in chunk
                    uint32_t bf[2];
                    bf[0] = f2u(fs[OKo + nrow * KSTR + kk]);
                    bf[1] = f2u(fs[OKo + nrow * KSTR + kk + 4]);
                    mma8(sfrag[nb], a, bf);
                }
            }
            // mask + store S
            int grow0 = q0 + 16 * rg + lrow;
            #pragma unroll
            for (int nb = 0; nb < 4; nb++) {
                int cb0 = 32 * h + nb * 8 + 2 * lcol;
                float2 v0 = make_float2(sfrag[nb][0], sfrag[nb][1]);
                float2 v1 = make_float2(sfrag[nb][2], sfrag[nb][3]);
                if (maskc) {
                    int g = k0 + cb0;
                    if (g > grow0)         v0.x = -1e30f;
                    if (g + 1 > grow0)     v0.y = -1e30f;
                    if (g > grow0 + 8)     v1.x = -1e30f;
                    if (g + 1 > grow0 + 8) v1.y = -1e30f;
                }
                *(float2*)&fs[OS + (16 * rg + lrow) * SSTR + cb0] = v0;
                *(float2*)&fs[OS + (16 * rg + lrow + 8) * SSTR + cb0] = v1;
            }
        }
        __syncthreads();   // (B) scores visible

        // ---- online softmax: 4 threads per row, 16 cols each ----
        {
            int row = tid >> 2, seg = tid & 3;
            float* Sr = &fs[OS + row * SSTR + seg * 16];
            float4 x0 = ((float4*)Sr)[0];
            float4 x1 = ((float4*)Sr)[1];
            float4 x2 = ((float4*)Sr)[2];
            float4 x3 = ((float4*)Sr)[3];
            float mx = fmaxf(fmaxf(fmaxf(x0.x, x0.y), fmaxf(x0.z, x0.w)),
                       fmaxf(fmaxf(fmaxf(x1.x, x1.y), fmaxf(x1.z, x1.w)),
                       fmaxf(fmaxf(fmaxf(x2.x, x2.y), fmaxf(x2.z, x2.w)),
                             fmaxf(fmaxf(x3.x, x3.y), fmaxf(x3.z, x3.w)))));
            mx = fmaxf(mx, __shfl_xor_sync(0xffffffff, mx, 1));
            mx = fmaxf(mx, __shfl_xor_sync(0xffffffff, mx, 2));
            float mold = fs[OM + row];
            float mnew = fmaxf(mold, mx);
            float alpha = __expf(mold - mnew);
            float sum = 0.0f;
            #pragma unroll
            for (int q = 0; q < 4; q++) {
                float4* xp = (q == 0) ? &x0 : (q == 1) ? &x1 : (q == 2) ? &x2 : &x3;
                xp->x = __expf(xp->x - mnew); sum += xp->x; xp->x = tf32r(xp->x);
                xp->y = __expf(xp->y - mnew); sum += xp->y; xp->y = tf32r(xp->y);
                xp->z = __expf(xp->z - mnew); sum += xp->z; xp->z = tf32r(xp->z);
                xp->w = __expf(xp->w - mnew); sum += xp->w; xp->w = tf32r(xp->w);
            }
            ((float4*)Sr)[0] = x0; ((float4*)Sr)[1] = x1;
            ((float4*)Sr)[2] = x2; ((float4*)Sr)[3] = x3;
            sum += __shfl_xor_sync(0xffffffff, sum, 1);
            sum += __shfl_xor_sync(0xffffffff, sum, 2);
            if (seg == 0) {
                fs[OL + row] = fs[OL + row] * alpha + sum;
                fs[OM + row] = mnew;
                fs[OA + row] = alpha;
            }
        }
        __syncthreads();   // (C) P + alpha visible

        // ---- PV: warp (rg,h): O[16rg..+15][128h..+127] += P * V ----
        {
            float al0 = fs[OA + 16 * rg + lrow];
            float al8 = fs[OA + 16 * rg + lrow + 8];
            #pragma unroll
            for (int nb = 0; nb < 16; nb++) {
                ofrag[nb][0] *= al0; ofrag[nb][1] *= al0;
                ofrag[nb][2] *= al8; ofrag[nb][3] *= al8;
            }
            int prow = 16 * rg + lrow;
            #pragma unroll
            for (int kb = 0; kb < 8; kb++) {
                int kk = kb * 8 + lcol;
                uint32_t a[4];
                a[0] = f2u(fs[OS + prow * SSTR + kk]);
                a[1] = f2u(fs[OS + (prow + 8) * SSTR + kk]);
                a[2] = f2u(fs[OS + prow * SSTR + kk + 4]);
                a[3] = f2u(fs[OS + (prow + 8) * SSTR + kk + 4]);
                #pragma unroll
                for (int nb = 0; nb < 16; nb++) {
                    int ncol = 128 * h + nb * 8 + lrow;
                    uint32_t bf[2];
                    bf[0] = f2u(fs[OV + kk * VSTR + ncol]);
                    bf[1] = f2u(fs[OV + (kk + 4) * VSTR + ncol]);
                    mma8(ofrag[nb], a, bf);
                }
            }
        }
        __syncthreads();   // (D) protect Ss/Vs/Ks before next staging
    }

    // ---- epilogue ----
    {
        int row = 16 * rg + lrow;
        float inv0 = 1.0f / fs[OL + row];
        float inv8 = 1.0f / fs[OL + row + 8];
        float* Or0 = Og + ((size_t)b * SS + q0 + row) * DD;
        float* Or8 = Or0 + 8 * DD;
        #pragma unroll
        for (int nb = 0; nb < 16; nb++) {
            int col = 128 * h + nb * 8 + 2 * lcol;
            *(float2*)&Or0[col] = make_float2(ofrag[nb][0] * inv0, ofrag[nb][1] * inv0);
            *(float2*)&Or8[col] = make_float2(ofrag[nb][2] * inv8, ofrag[nb][3] * inv8);
        }
    }
}

// ============================================================
// tf32 HMMA GEMM: C[M,N] = A[M,K] * W[K,N] (+bias, +leaky)
// BM=64, BN=64, BK=16, 256 threads (8 warps = 4m x 2n).
// M%64==0, K%16==0 required; N guarded.
// ============================================================
#define ASTR 20
#define WSTR 72

template<int BIAS, int LEAKY>
__global__ void __launch_bounds__(256)
gemm_tc(const float* __restrict__ A, const float* __restrict__ W,
        const float* __restrict__ bias, float* __restrict__ C,
        int M, int N, int K) {
    __shared__ float As[64 * ASTR];
    __shared__ float Ws[16 * WSTR];
    int tid = threadIdx.x;
    int wid = tid >> 5, lane = tid & 31;
    int wm = wid & 3, wn = wid >> 2;
    int lrow = lane >> 2, lcol = lane & 3;
    int rb = blockIdx.y * 64, cb = blockIdx.x * 64;

    float cfr[4][4];
    #pragma unroll
    for (int nb = 0; nb < 4; nb++)
        #pragma unroll
        for (int j = 0; j < 4; j++) cfr[nb][j] = 0.0f;

    for (int k0 = 0; k0 < K; k0 += 16) {
        // stage A tile 64x16
        {
            int row = tid >> 2, kq = tid & 3;
            float4 v = *(const float4*)&A[(size_t)(rb + row) * K + k0 + kq * 4];
            v.x = tf32r(v.x); v.y = tf32r(v.y); v.z = tf32r(v.z); v.w = tf32r(v.w);
            *(float4*)&As[row * ASTR + kq * 4] = v;
        }
        // stage W tile 16x64
        {
            int kk = tid >> 4, n4 = tid & 15;
            int col = cb + n4 * 4;
            float4 v;
            if (col + 3 < N) {
                v = *(const float4*)&W[(size_t)(k0 + kk) * N + col];
            } else {
                v.x = (col + 0 < N) ? W[(size_t)(k0 + kk) * N + col + 0] : 0.0f;
                v.y = (col + 1 < N) ? W[(size_t)(k0 + kk) * N + col + 1] : 0.0f;
                v.z = (col + 2 < N) ? W[(size_t)(k0 + kk) * N + col + 2] : 0.0f;
                v.w = (col + 3 < N) ? W[(size_t)(k0 + kk) * N + col + 3] : 0.0f;
            }
            v.x = tf32r(v.x); v.y = tf32r(v.y); v.z = tf32r(v.z); v.w = tf32r(v.w);
            *(float4*)&Ws[kk * WSTR + n4 * 4] = v;
        }
        __syncthreads();
        #pragma unroll
        for (int kb = 0; kb < 2; kb++) {
            int kk = kb * 8 + lcol;
            uint32_t a[4];
            a[0] = f2u(As[(16 * wm + lrow) * ASTR + kk]);
            a[1] = f2u(As[(16 * wm + lrow + 8) * ASTR + kk]);
            a[2] = f2u(As[(16 * wm + lrow) * ASTR + kk + 4]);
            a[3] = f2u(As[(16 * wm + lrow + 8) * ASTR + kk + 4]);
            #pragma unroll
            for (int nb = 0; nb < 4; nb++) {
                int ncol = 32 * wn + nb * 8 + lrow;
                uint32_t bf[2];
                bf[0] = f2u(Ws[kk * WSTR + ncol]);
                bf[1] = f2u(Ws[(kk + 4) * WSTR + ncol]);
                mma8(cfr[nb], a, bf);
            }
        }
        __syncthreads();
    }

    // epilogue
    int r0 = rb + 16 * wm + lrow;
    #pragma unroll
    for (int nb = 0; nb < 4; nb++) {
        int col = cb + 32 * wn + nb * 8 + 2 * lcol;
        if (col < N) {
            float v00 = cfr[nb][0], v01 = cfr[nb][1];
            float v10 = cfr[nb][2], v11 = cfr[nb][3];
            if (BIAS) {
                float b0 = bias[col], b1 = bias[col + 1];
                v00 += b0; v01 += b1; v10 += b0; v11 += b1;
            }
            if (LEAKY) {
                v00 = (v00 > 0.0f) ? v00 : 0.2f * v00;
                v01 = (v01 > 0.0f) ? v01 : 0.2f * v01;
                v10 = (v10 > 0.0f) ? v10 : 0.2f * v10;
                v11 = (v11 > 0.0f) ? v11 : 0.2f * v11;
            }
            *(float2*)&C[(size_t)r0 * N + col] = make_float2(v00, v01);
            *(float2*)&C[(size_t)(r0 + 8) * N + col] = make_float2(v10, v11);
        }
    }
}

// ============================================================
// out = LayerNorm(a + b), eps = 1e-3
// ============================================================
__global__ void add_ln_kernel(const float* __restrict__ a, const float* __restrict__ bvec,
                              const float* __restrict__ gamma, const float* __restrict__ beta,
                              float* __restrict__ out) {
    int row = blockIdx.x;
    int d = threadIdx.x;
    float v = a[row * DD + d] + bvec[row * DD + d];

    __shared__ float red[8];
    float sum = v;
    #pragma unroll
    for (int off = 16; off > 0; off >>= 1) sum += __shfl_xor_sync(0xffffffff, sum, off);
    if ((d & 31) == 0) red[d >> 5] = sum;
    __syncthreads();
    float tot = 0.0f;
    #pragma unroll
    for (int i = 0; i < 8; i++) tot += red[i];
    float mu = tot * (1.0f / DD);

    float dv = v - mu;
    float sq = dv * dv;
    #pragma unroll
    for (int off = 16; off > 0; off >>= 1) sq += __shfl_xor_sync(0xffffffff, sq, off);
    __syncthreads();
    if ((d & 31) == 0) red[d >> 5] = sq;
    __syncthreads();
    float var = 0.0f;
    #pragma unroll
    for (int i = 0; i < 8; i++) var += red[i];
    var *= (1.0f / DD);

    out[row * DD + d] = dv * rsqrtf(var + 1e-3f) * gamma[d] + beta[d];
}

// ============================================================
extern "C" void kernel_launch(void* const* d_in, const int* in_sizes, int n_in,
                              void* d_out, int out_size) {
    const float* inputs = (const float*)d_in[0];
    const float* ctx    = (const float*)d_in[1];
    const float* sa_Wk  = (const float*)d_in[2];
    const float* sa_Wv  = (const float*)d_in[3];
    const float* sa_Wq  = (const float*)d_in[4];
    const float* ca_Wk  = (const float*)d_in[5];
    const float* ca_Wv  = (const float*)d_in[6];
    const float* ca_Wq  = (const float*)d_in[7];
    const float* W1     = (const float*)d_in[8];
    const float* b1     = (const float*)d_in[9];
    const float* W2     = (const float*)d_in[10];
    const float* b2     = (const float*)d_in[11];
    const float* gamma  = (const float*)d_in[12];
    const float* beta   = (const float*)d_in[13];
    float* out = (float*)d_out;

    float *Qp, *Kp, *Vp, *Tp, *Xp, *Yp, *Hp;
    cudaGetSymbolAddress((void**)&Qp, g_Q);
    cudaGetSymbolAddress((void**)&Kp, g_K);
    cudaGetSymbolAddress((void**)&Vp, g_V);
    cudaGetSymbolAddress((void**)&Tp, g_T);
    cudaGetSymbolAddress((void**)&Xp, g_X);
    cudaGetSymbolAddress((void**)&Yp, g_Y);
    cudaGetSymbolAddress((void**)&Hp, g_H);

    const int flash_smem = FL_FLOATS * 4;
    cudaFuncSetAttribute(flash_mma, cudaFuncAttributeMaxDynamicSharedMemorySize, flash_smem);

    dim3 gD(DD / 64, BSROWS / 64);
    dim3 gH((HH + 63) / 64, BSROWS / 64);
    dim3 fg(SS / FBQ, BB);

    // 1) self-attention (causal)
    gemm_tc<0, 0><<<gD, 256>>>(inputs, sa_Wk, nullptr, Kp, BSROWS, DD, DD);
    gemm_tc<0, 0><<<gD, 256>>>(inputs, sa_Wv, nullptr, Vp, BSROWS, DD, DD);
    gemm_tc<0, 0><<<gD, 256>>>(inputs, sa_Wq, nullptr, Qp, BSROWS, DD, DD);
    flash_mma<<<fg, 256, flash_smem>>>(Qp, Kp, Vp, Tp, 1);
    add_ln_kernel<<<BSROWS, 256>>>(Tp, inputs, gamma, beta, Xp);

    // 2) cross-attention
    gemm_tc<0, 0><<<gD, 256>>>(ctx, ca_Wk, nullptr, Kp, BSROWS, DD, DD);
    gemm_tc<0, 0><<<gD, 256>>>(ctx, ca_Wv, nullptr, Vp, BSROWS, DD, DD);
    gemm_tc<0, 0><<<gD, 256>>>(Xp, ca_Wq, nullptr, Qp, BSROWS, DD, DD);
    flash_mma<<<fg, 256, flash_smem>>>(Qp, Kp, Vp, Tp, 0);
    add_ln_kernel<<<BSROWS, 256>>>(Tp, Xp, gamma, beta, Yp);

    // 3) FFN
    gemm_tc<1, 1><<<gH, 256>>>(Yp, W1, b1, Hp, BSROWS, HH, DD);
    gemm_tc<1, 0><<<gD, 256>>>(Hp, W2, b2, Tp, BSROWS, DD, HH);
    add_ln_kernel<<<BSROWS, 256>>>(Tp, Yp, gamma, beta, out);
}